// round 1
// baseline (speedup 1.0000x reference)
#include <cuda_runtime.h>
#include <cstdint>

#define LEAKY 0.2f
#define B_ 4
#define H_ 4
#define N_ 4096
#define F_ 64
#define U_ 32
#define BH_ (B_*H_)
#define NC16 (N_/16)   // 256 chunks of 16 per (b,h)

// ---------------- scratch (device globals; no allocations) ----------------
__device__ float g_feats[BH_ * N_ * U_];   // [bh][n][u] per-head projected features
__device__ float g_s[BH_ * N_];            // a_self per node (original order)
__device__ float g_t[BH_ * N_];            // a_neigh per node (original order)
__device__ float g_ts[BH_ * N_];           // sorted t (ascending)
__device__ int   g_perm[BH_ * N_];         // sorted order -> original index
__device__ float g_w1[BH_ * N_];           // exp(t_sorted)
__device__ float g_w2[BH_ * N_];           // exp(alpha * t_sorted)
__device__ float g_S1[BH_ * N_];           // inclusive prefix of w1 (scalar)
__device__ float g_S2[BH_ * N_];           // inclusive prefix of w2 (scalar)
__device__ float g_P1[BH_ * N_ * U_];      // within-16-chunk inclusive prefix of w1*feats
__device__ float g_P2[BH_ * N_ * U_];      // within-16-chunk inclusive prefix of w2*feats
__device__ float g_T1[BH_ * NC16 * U_];    // 16-chunk totals
__device__ float g_T2[BH_ * NC16 * U_];
__device__ float g_O1[BH_ * NC16 * U_];    // exclusive chunk offsets
__device__ float g_O2[BH_ * NC16 * U_];
__device__ float g_Ptot1[BH_ * U_];        // grand totals of w1*feats

// ============================================================
// k1: feats[bh][n][u] = sum_f x[b][n][f]*K[h][f][u];  s,t projections
// grid (N/128, BH), block 128
// ============================================================
__global__ void k1_feats(const float* __restrict__ x,
                         const float* __restrict__ kern,
                         const float* __restrict__ att_s,
                         const float* __restrict__ att_n) {
    __shared__ float  xs[128][F_ + 1];
    __shared__ float4 ks4[F_ * (U_ / 4)];
    __shared__ float  as_s[U_], as_n[U_];

    const int bh = blockIdx.y;
    const int b = bh / H_, h = bh % H_;
    const int tid = threadIdx.x;

    // load K[h] (64x32 f32 = 8KB) as float4
    const float4* ksrc = (const float4*)(kern + (size_t)h * F_ * U_);
    for (int i = tid; i < F_ * (U_ / 4); i += 128) ks4[i] = ksrc[i];
    if (tid < U_) { as_s[tid] = att_s[h * U_ + tid]; as_n[tid] = att_n[h * U_ + tid]; }

    // load x tile [128 rows x 64 f]
    const int n0 = blockIdx.x * 128;
    const float* xb = x + ((size_t)b * N_ + n0) * F_;
    for (int i = tid; i < 128 * F_; i += 128) xs[i >> 6][i & 63] = xb[i];
    __syncthreads();

    float acc[U_];
#pragma unroll
    for (int u = 0; u < U_; u++) acc[u] = 0.f;

#pragma unroll 4
    for (int f = 0; f < F_; f++) {
        const float xv = xs[tid][f];
#pragma unroll
        for (int u4 = 0; u4 < U_ / 4; u4++) {
            const float4 kv = ks4[f * (U_ / 4) + u4];
            acc[u4 * 4 + 0] += xv * kv.x;
            acc[u4 * 4 + 1] += xv * kv.y;
            acc[u4 * 4 + 2] += xv * kv.z;
            acc[u4 * 4 + 3] += xv * kv.w;
        }
    }

    const int n = n0 + tid;
    float* fo = g_feats + ((size_t)bh * N_ + n) * U_;
#pragma unroll
    for (int u4 = 0; u4 < U_ / 4; u4++) {
        ((float4*)fo)[u4] = make_float4(acc[u4*4], acc[u4*4+1], acc[u4*4+2], acc[u4*4+3]);
    }
    float s = 0.f, t = 0.f;
#pragma unroll
    for (int u = 0; u < U_; u++) { s += acc[u] * as_s[u]; t += acc[u] * as_n[u]; }
    g_s[bh * N_ + n] = s;
    g_t[bh * N_ + n] = t;
}

// ============================================================
// k2: per-(b,h) bitonic sort of 4096 packed (key<<32 | idx),
//     then block-wide inclusive scalar scans of exp(t), exp(a*t).
// grid BH, block 1024
// ============================================================
__global__ void k2_sort_scan() {
    __shared__ unsigned long long sm[N_];
    __shared__ float w1s[32], w2s[32];

    const int bh = blockIdx.x;
    const int tid = threadIdx.x;

    for (int i = tid; i < N_; i += 1024) {
        unsigned int f = __float_as_uint(g_t[bh * N_ + i]);
        unsigned int u = (f & 0x80000000u) ? ~f : (f ^ 0x80000000u); // sortable transform
        sm[i] = ((unsigned long long)u << 32) | (unsigned int)i;
    }
    __syncthreads();

    for (int k = 2; k <= N_; k <<= 1) {
        for (int j = k >> 1; j > 0; j >>= 1) {
#pragma unroll
            for (int r = 0; r < N_ / 1024; r++) {
                const int i = tid + r * 1024;
                const int ixj = i ^ j;
                if (ixj > i) {
                    const unsigned long long a = sm[i], c = sm[ixj];
                    const bool up = ((i & k) == 0);
                    if ((a > c) == up) { sm[i] = c; sm[ixj] = a; }
                }
            }
            __syncthreads();
        }
    }

    // unpack, write sorted arrays, build weights + inclusive scalar scans
    const int base = tid * 4;
    float l1[4], l2[4];
    float r1 = 0.f, r2 = 0.f;
#pragma unroll
    for (int i = 0; i < 4; i++) {
        const unsigned long long p = sm[base + i];
        const unsigned int u = (unsigned int)(p >> 32);
        const unsigned int f = (u & 0x80000000u) ? (u ^ 0x80000000u) : ~u;
        const float tv = __uint_as_float(f);
        const int src = (int)(p & 0xffffffffu);
        g_ts[bh * N_ + base + i] = tv;
        g_perm[bh * N_ + base + i] = src;
        const float w1 = expf(tv);
        const float w2 = expf(LEAKY * tv);
        g_w1[bh * N_ + base + i] = w1;
        g_w2[bh * N_ + base + i] = w2;
        r1 += w1; r2 += w2;
        l1[i] = r1; l2[i] = r2;
    }
    // warp inclusive scan of per-thread totals
    const int lane = tid & 31, wid = tid >> 5;
    float t1 = r1, t2 = r2;
#pragma unroll
    for (int off = 1; off < 32; off <<= 1) {
        const float a = __shfl_up_sync(0xffffffffu, t1, off);
        const float c = __shfl_up_sync(0xffffffffu, t2, off);
        if (lane >= off) { t1 += a; t2 += c; }
    }
    if (lane == 31) { w1s[wid] = t1; w2s[wid] = t2; }
    __syncthreads();
    if (wid == 0) {
        float a1 = w1s[lane], a2 = w2s[lane];
        float s1 = a1, s2 = a2;
#pragma unroll
        for (int off = 1; off < 32; off <<= 1) {
            const float x1 = __shfl_up_sync(0xffffffffu, s1, off);
            const float x2 = __shfl_up_sync(0xffffffffu, s2, off);
            if (lane >= off) { s1 += x1; s2 += x2; }
        }
        w1s[lane] = s1 - a1;   // exclusive warp offsets
        w2s[lane] = s2 - a2;
    }
    __syncthreads();
    const float base1 = (t1 - r1) + w1s[wid];
    const float base2 = (t2 - r2) + w2s[wid];
#pragma unroll
    for (int i = 0; i < 4; i++) {
        g_S1[bh * N_ + base + i] = l1[i] + base1;
        g_S2[bh * N_ + base + i] = l2[i] + base2;
    }
}

// ============================================================
// k3a: within-16-chunk inclusive prefix of w*feats (gathered by perm).
// grid (BH, 32) each block covers 128 sorted positions; block 256 = 8 warps,
// warp -> 16 consecutive j, lane -> u.
// ============================================================
__global__ void k3a_chunk_prefix() {
    const int bh = blockIdx.x;
    const int w = threadIdx.x >> 5, lane = threadIdx.x & 31;
    const int j0 = blockIdx.y * 128 + w * 16;

    const float* fe = g_feats + (size_t)bh * N_ * U_;
    float* P1 = g_P1 + (size_t)bh * N_ * U_;
    float* P2 = g_P2 + (size_t)bh * N_ * U_;

    float a1 = 0.f, a2 = 0.f;
#pragma unroll
    for (int i = 0; i < 16; i++) {
        const int jj = j0 + i;
        const int p = __ldg(&g_perm[bh * N_ + jj]);
        const float w1 = __ldg(&g_w1[bh * N_ + jj]);
        const float w2 = __ldg(&g_w2[bh * N_ + jj]);
        const float v = __ldg(&fe[p * U_ + lane]);
        a1 += w1 * v;
        a2 += w2 * v;
        P1[jj * U_ + lane] = a1;
        P2[jj * U_ + lane] = a2;
    }
    const int c16 = j0 >> 4;
    g_T1[((size_t)bh * NC16 + c16) * U_ + lane] = a1;
    g_T2[((size_t)bh * NC16 + c16) * U_ + lane] = a2;
}

// ============================================================
// k3b: exclusive scan of 256 chunk totals per (bh,u) + grand totals.
// grid BH, block 1024 = 32 warps; warp -> u, lane handles 8 chunks.
// ============================================================
__global__ void k3b_chunk_scan() {
    const int bh = blockIdx.x;
    const int u = threadIdx.x >> 5;
    const int lane = threadIdx.x & 31;

    float v1[8], v2[8], l1[8], l2[8];
    float r1 = 0.f, r2 = 0.f;
#pragma unroll
    for (int i = 0; i < 8; i++) {
        const int ch = lane * 8 + i;
        const float a = g_T1[((size_t)bh * NC16 + ch) * U_ + u];
        const float c = g_T2[((size_t)bh * NC16 + ch) * U_ + u];
        r1 += a; r2 += c;
        v1[i] = a; v2[i] = c;
        l1[i] = r1; l2[i] = r2;
    }
    float t1 = r1, t2 = r2;
#pragma unroll
    for (int off = 1; off < 32; off <<= 1) {
        const float x1 = __shfl_up_sync(0xffffffffu, t1, off);
        const float x2 = __shfl_up_sync(0xffffffffu, t2, off);
        if (lane >= off) { t1 += x1; t2 += x2; }
    }
    const float e1 = t1 - r1, e2 = t2 - r2; // exclusive across lanes
#pragma unroll
    for (int i = 0; i < 8; i++) {
        const int ch = lane * 8 + i;
        g_O1[((size_t)bh * NC16 + ch) * U_ + u] = e1 + (i ? l1[i - 1] : 0.f);
        g_O2[((size_t)bh * NC16 + ch) * U_ + u] = e2 + (i ? l2[i - 1] : 0.f);
    }
    const float tot1 = __shfl_sync(0xffffffffu, t1, 31);
    if (lane == 0) g_Ptot1[bh * U_ + u] = tot1;
}

// ============================================================
// k4: per-node combine. warp -> one n, lane -> u.
// grid BH*N/8, block 256
// ============================================================
__global__ void k4_output(const float* __restrict__ biases, float* __restrict__ out) {
    const int gw = blockIdx.x * 8 + (threadIdx.x >> 5);
    const int lane = threadIdx.x & 31;
    const int bh = gw >> 12;        // / N_
    const int n = gw & (N_ - 1);
    const int b = bh >> 2, h = bh & (H_ - 1);

    const float c = g_s[bh * N_ + n];
    const float th = -c;
    const float* ts = g_ts + bh * N_;

    // lower_bound: first k with ts[k] >= th  (all lanes identical -> broadcast loads)
    int lo = 0, hi = N_;
    while (lo < hi) {
        const int mid = (lo + hi) >> 1;
        if (__ldg(&ts[mid]) < th) lo = mid + 1; else hi = mid;
    }
    const int k = lo;

    const float ea = expf(LEAKY * c);
    const float eb = expf(c);

    const float S1t = __ldg(&g_S1[bh * N_ + N_ - 1]);
    float S1ex = 0.f, S2ex = 0.f, p1 = 0.f, p2 = 0.f;
    if (k > 0) {
        const int km = k - 1;
        S1ex = __ldg(&g_S1[bh * N_ + km]);
        S2ex = __ldg(&g_S2[bh * N_ + km]);
        const int c16 = km >> 4;
        p1 = __ldg(&g_P1[((size_t)bh * N_ + km) * U_ + lane])
           + __ldg(&g_O1[((size_t)bh * NC16 + c16) * U_ + lane]);
        p2 = __ldg(&g_P2[((size_t)bh * N_ + km) * U_ + lane])
           + __ldg(&g_O2[((size_t)bh * NC16 + c16) * U_ + lane]);
    }
    const float pt1 = __ldg(&g_Ptot1[bh * U_ + lane]);

    const float Z = ea * S2ex + eb * (S1t - S1ex);
    const float num = ea * p2 + eb * (pt1 - p1);
    const float val = num / Z + __ldg(&biases[h * U_ + lane]);

    out[((size_t)b * N_ + n) * (H_ * U_) + h * U_ + lane] = fmaxf(val, 0.f);
}

// ============================================================
extern "C" void kernel_launch(void* const* d_in, const int* in_sizes, int n_in,
                              void* d_out, int out_size) {
    const float* x      = (const float*)d_in[0];
    const float* kern   = (const float*)d_in[1];
    const float* att_s  = (const float*)d_in[2];
    const float* att_n  = (const float*)d_in[3];
    const float* biases = (const float*)d_in[4];
    float* out = (float*)d_out;

    k1_feats<<<dim3(N_ / 128, BH_), 128>>>(x, kern, att_s, att_n);
    k2_sort_scan<<<BH_, 1024>>>();
    k3a_chunk_prefix<<<dim3(BH_, 32), 256>>>();
    k3b_chunk_scan<<<BH_, 1024>>>();
    k4_output<<<(BH_ * N_) / 8, 256>>>(biases, out);
}

// round 2
// speedup vs baseline: 1.4904x; 1.4904x over previous
#include <cuda_runtime.h>
#include <cstdint>

#define LEAKY 0.2f
#define B_ 4
#define H_ 4
#define N_ 4096
#define F_ 64
#define U_ 32
#define BH_ (B_*H_)
#define NC16 (N_/16)   // 256 chunks of 16 per (b,h)

// ---------------- scratch (device globals; no allocations) ----------------
__device__ float g_feats[BH_ * N_ * U_];   // [bh][n][u] per-head projected features
__device__ float g_s[BH_ * N_];            // a_self per node (original order)
__device__ float g_t[BH_ * N_];            // a_neigh per node (original order)
__device__ float g_ts[BH_ * N_];           // sorted t (ascending)
__device__ int   g_perm[BH_ * N_];         // sorted order -> original index
__device__ float g_w1[BH_ * N_];           // exp(t_sorted)
__device__ float g_w2[BH_ * N_];           // exp(alpha * t_sorted)
__device__ float g_S1[BH_ * N_];           // inclusive prefix of w1 (scalar)
__device__ float g_S2[BH_ * N_];           // inclusive prefix of w2 (scalar)
__device__ float g_P1[BH_ * N_ * U_];      // within-16-chunk inclusive prefix of w1*feats
__device__ float g_P2[BH_ * N_ * U_];      // within-16-chunk inclusive prefix of w2*feats
__device__ float g_T1[BH_ * NC16 * U_];    // 16-chunk totals
__device__ float g_T2[BH_ * NC16 * U_];
__device__ float g_O1[BH_ * NC16 * U_];    // exclusive chunk offsets
__device__ float g_O2[BH_ * NC16 * U_];
__device__ float g_Ptot1[BH_ * U_];        // grand totals of w1*feats

// ============================================================
// k1: feats[bh][n][u] = sum_f x[b][n][f]*K[h][f][u];  s,t projections
// grid (N/128, BH), block 128
// ============================================================
__global__ void k1_feats(const float* __restrict__ x,
                         const float* __restrict__ kern,
                         const float* __restrict__ att_s,
                         const float* __restrict__ att_n) {
    __shared__ float  xs[128][F_ + 1];
    __shared__ float4 ks4[F_ * (U_ / 4)];
    __shared__ float  as_s[U_], as_n[U_];

    const int bh = blockIdx.y;
    const int b = bh / H_, h = bh % H_;
    const int tid = threadIdx.x;

    const float4* ksrc = (const float4*)(kern + (size_t)h * F_ * U_);
    for (int i = tid; i < F_ * (U_ / 4); i += 128) ks4[i] = ksrc[i];
    if (tid < U_) { as_s[tid] = att_s[h * U_ + tid]; as_n[tid] = att_n[h * U_ + tid]; }

    const int n0 = blockIdx.x * 128;
    const float* xb = x + ((size_t)b * N_ + n0) * F_;
    for (int i = tid; i < 128 * F_; i += 128) xs[i >> 6][i & 63] = xb[i];
    __syncthreads();

    float acc[U_];
#pragma unroll
    for (int u = 0; u < U_; u++) acc[u] = 0.f;

#pragma unroll 4
    for (int f = 0; f < F_; f++) {
        const float xv = xs[tid][f];
#pragma unroll
        for (int u4 = 0; u4 < U_ / 4; u4++) {
            const float4 kv = ks4[f * (U_ / 4) + u4];
            acc[u4 * 4 + 0] += xv * kv.x;
            acc[u4 * 4 + 1] += xv * kv.y;
            acc[u4 * 4 + 2] += xv * kv.z;
            acc[u4 * 4 + 3] += xv * kv.w;
        }
    }

    const int n = n0 + tid;
    float* fo = g_feats + ((size_t)bh * N_ + n) * U_;
#pragma unroll
    for (int u4 = 0; u4 < U_ / 4; u4++) {
        ((float4*)fo)[u4] = make_float4(acc[u4*4], acc[u4*4+1], acc[u4*4+2], acc[u4*4+3]);
    }
    float s = 0.f, t = 0.f;
#pragma unroll
    for (int u = 0; u < U_; u++) { s += acc[u] * as_s[u]; t += acc[u] * as_n[u]; }
    g_s[bh * N_ + n] = s;
    g_t[bh * N_ + n] = t;
}

// ============================================================
// k2: per-(b,h) bitonic sort of 4096 packed (key<<32 | idx).
// Register/shfl bitonic: thread owns 4 consecutive elements; stages
// j<=2 in-register, j=4..64 via shfl_xor, only j>=128 via smem+bar.
// Then block-wide inclusive scalar scans of exp(t), exp(a*t).
// grid BH, block 1024
// ============================================================
__device__ __forceinline__ void cmpswap_ull(unsigned long long& a,
                                            unsigned long long& b, bool asc) {
    if ((a > b) == asc) { unsigned long long t = a; a = b; b = t; }
}

__global__ void k2_sort_scan() {
    __shared__ unsigned long long sm[N_];
    __shared__ float w1s[32], w2s[32];

    const int bh = blockIdx.x;
    const int tid = threadIdx.x;
    const int lane = tid & 31, wid = tid >> 5;
    const int base = tid * 4;

    unsigned long long v[4];
#pragma unroll
    for (int e = 0; e < 4; e++) {
        const int i = base + e;
        unsigned int f = __float_as_uint(g_t[bh * N_ + i]);
        unsigned int u = (f & 0x80000000u) ? ~f : (f ^ 0x80000000u); // sortable
        v[e] = ((unsigned long long)u << 32) | (unsigned int)i;
    }

    // phase k=2 (within-thread, per-element direction)
    cmpswap_ull(v[0], v[1], true);
    cmpswap_ull(v[2], v[3], false);

    // phases k=4..128: registers + shfl only (no barriers)
#pragma unroll
    for (int k = 4; k <= 128; k <<= 1) {
        const bool dir = ((base & k) == 0);
#pragma unroll
        for (int j = 64; j >= 4; j >>= 1) {
            if (j <= (k >> 1)) {
                const int lj = j >> 2;
                const bool takeMin = (((lane & lj) == 0) == dir);
#pragma unroll
                for (int e = 0; e < 4; e++) {
                    unsigned long long other = __shfl_xor_sync(0xffffffffu, v[e], lj);
                    v[e] = ((v[e] < other) == takeMin) ? v[e] : other;
                }
            }
        }
        cmpswap_ull(v[0], v[2], dir); cmpswap_ull(v[1], v[3], dir);
        cmpswap_ull(v[0], v[1], dir); cmpswap_ull(v[2], v[3], dir);
    }

    // phases k=256..4096: smem for j>=128, then regs/shfl for j<=64
    for (int k = 256; k <= N_; k <<= 1) {
#pragma unroll
        for (int e = 0; e < 4; e++) sm[base + e] = v[e];
        __syncthreads();
        for (int j = k >> 1; j >= 128; j >>= 1) {
#pragma unroll
            for (int r = 0; r < N_ / 1024; r++) {
                const int i = tid + r * 1024;
                const int ixj = i ^ j;
                if (ixj > i) {
                    const unsigned long long a = sm[i], c = sm[ixj];
                    const bool up = ((i & k) == 0);
                    if ((a > c) == up) { sm[i] = c; sm[ixj] = a; }
                }
            }
            __syncthreads();
        }
#pragma unroll
        for (int e = 0; e < 4; e++) v[e] = sm[base + e];
        const bool dir = ((base & k) == 0);
#pragma unroll
        for (int j = 64; j >= 4; j >>= 1) {
            const int lj = j >> 2;
            const bool takeMin = (((lane & lj) == 0) == dir);
#pragma unroll
            for (int e = 0; e < 4; e++) {
                unsigned long long other = __shfl_xor_sync(0xffffffffu, v[e], lj);
                v[e] = ((v[e] < other) == takeMin) ? v[e] : other;
            }
        }
        cmpswap_ull(v[0], v[2], dir); cmpswap_ull(v[1], v[3], dir);
        cmpswap_ull(v[0], v[1], dir); cmpswap_ull(v[2], v[3], dir);
    }

    // unpack (sorted data now in regs), write sorted arrays,
    // build weights + inclusive scalar scans
    float l1[4], l2[4];
    float r1 = 0.f, r2 = 0.f;
#pragma unroll
    for (int i = 0; i < 4; i++) {
        const unsigned long long p = v[i];
        const unsigned int u = (unsigned int)(p >> 32);
        const unsigned int f = (u & 0x80000000u) ? (u ^ 0x80000000u) : ~u;
        const float tv = __uint_as_float(f);
        const int src = (int)(p & 0xffffffffu);
        g_ts[bh * N_ + base + i] = tv;
        g_perm[bh * N_ + base + i] = src;
        const float w1 = expf(tv);
        const float w2 = expf(LEAKY * tv);
        g_w1[bh * N_ + base + i] = w1;
        g_w2[bh * N_ + base + i] = w2;
        r1 += w1; r2 += w2;
        l1[i] = r1; l2[i] = r2;
    }
    float t1 = r1, t2 = r2;
#pragma unroll
    for (int off = 1; off < 32; off <<= 1) {
        const float a = __shfl_up_sync(0xffffffffu, t1, off);
        const float c = __shfl_up_sync(0xffffffffu, t2, off);
        if (lane >= off) { t1 += a; t2 += c; }
    }
    if (lane == 31) { w1s[wid] = t1; w2s[wid] = t2; }
    __syncthreads();
    if (wid == 0) {
        float a1 = w1s[lane], a2 = w2s[lane];
        float s1 = a1, s2 = a2;
#pragma unroll
        for (int off = 1; off < 32; off <<= 1) {
            const float x1 = __shfl_up_sync(0xffffffffu, s1, off);
            const float x2 = __shfl_up_sync(0xffffffffu, s2, off);
            if (lane >= off) { s1 += x1; s2 += x2; }
        }
        w1s[lane] = s1 - a1;   // exclusive warp offsets
        w2s[lane] = s2 - a2;
    }
    __syncthreads();
    const float base1 = (t1 - r1) + w1s[wid];
    const float base2 = (t2 - r2) + w2s[wid];
#pragma unroll
    for (int i = 0; i < 4; i++) {
        g_S1[bh * N_ + base + i] = l1[i] + base1;
        g_S2[bh * N_ + base + i] = l2[i] + base2;
    }
}

// ============================================================
// k3a: within-16-chunk inclusive prefix of w*feats (gathered by perm).
// grid (BH, 32) each block covers 128 sorted positions; block 256 = 8 warps,
// warp -> 16 consecutive j, lane -> u.
// ============================================================
__global__ void k3a_chunk_prefix() {
    const int bh = blockIdx.x;
    const int w = threadIdx.x >> 5, lane = threadIdx.x & 31;
    const int j0 = blockIdx.y * 128 + w * 16;

    const float* fe = g_feats + (size_t)bh * N_ * U_;
    float* P1 = g_P1 + (size_t)bh * N_ * U_;
    float* P2 = g_P2 + (size_t)bh * N_ * U_;

    float a1 = 0.f, a2 = 0.f;
#pragma unroll
    for (int i = 0; i < 16; i++) {
        const int jj = j0 + i;
        const int p = __ldg(&g_perm[bh * N_ + jj]);
        const float w1 = __ldg(&g_w1[bh * N_ + jj]);
        const float w2 = __ldg(&g_w2[bh * N_ + jj]);
        const float v = __ldg(&fe[p * U_ + lane]);
        a1 += w1 * v;
        a2 += w2 * v;
        P1[jj * U_ + lane] = a1;
        P2[jj * U_ + lane] = a2;
    }
    const int c16 = j0 >> 4;
    g_T1[((size_t)bh * NC16 + c16) * U_ + lane] = a1;
    g_T2[((size_t)bh * NC16 + c16) * U_ + lane] = a2;
}

// ============================================================
// k3b: exclusive scan of 256 chunk totals per (bh,u) + grand totals.
// COALESCED: warp w owns chunks [8w, 8w+8), lane -> u.
// grid BH, block 1024 = 32 warps.
// ============================================================
__global__ void k3b_chunk_scan() {
    __shared__ float s1[32 * 32], s2[32 * 32];
    const int bh = blockIdx.x;
    const int w = threadIdx.x >> 5, lane = threadIdx.x & 31;

    float e1[8], e2[8];
    float a1 = 0.f, a2 = 0.f;
#pragma unroll
    for (int i = 0; i < 8; i++) {
        const int ch = w * 8 + i;
        e1[i] = a1; e2[i] = a2;
        a1 += g_T1[((size_t)bh * NC16 + ch) * U_ + lane];
        a2 += g_T2[((size_t)bh * NC16 + ch) * U_ + lane];
    }
    s1[w * 32 + lane] = a1;
    s2[w * 32 + lane] = a2;
    __syncthreads();
    float off1 = 0.f, off2 = 0.f;
    for (int ww = 0; ww < w; ww++) {
        off1 += s1[ww * 32 + lane];
        off2 += s2[ww * 32 + lane];
    }
#pragma unroll
    for (int i = 0; i < 8; i++) {
        const int ch = w * 8 + i;
        g_O1[((size_t)bh * NC16 + ch) * U_ + lane] = off1 + e1[i];
        g_O2[((size_t)bh * NC16 + ch) * U_ + lane] = off2 + e2[i];
    }
    if (w == 31) g_Ptot1[bh * U_ + lane] = off1 + a1;
}

// ============================================================
// k4: per-node combine. warp -> one n, lane -> u.
// grid BH*N/8, block 256
// ============================================================
__global__ void k4_output(const float* __restrict__ biases, float* __restrict__ out) {
    const int gw = blockIdx.x * 8 + (threadIdx.x >> 5);
    const int lane = threadIdx.x & 31;
    const int bh = gw >> 12;        // / N_
    const int n = gw & (N_ - 1);
    const int b = bh >> 2, h = bh & (H_ - 1);

    const float c = g_s[bh * N_ + n];
    const float th = -c;
    const float* ts = g_ts + bh * N_;

    int lo = 0, hi = N_;
    while (lo < hi) {
        const int mid = (lo + hi) >> 1;
        if (__ldg(&ts[mid]) < th) lo = mid + 1; else hi = mid;
    }
    const int k = lo;

    const float ea = expf(LEAKY * c);
    const float eb = expf(c);

    const float S1t = __ldg(&g_S1[bh * N_ + N_ - 1]);
    float S1ex = 0.f, S2ex = 0.f, p1 = 0.f, p2 = 0.f;
    if (k > 0) {
        const int km = k - 1;
        S1ex = __ldg(&g_S1[bh * N_ + km]);
        S2ex = __ldg(&g_S2[bh * N_ + km]);
        const int c16 = km >> 4;
        p1 = __ldg(&g_P1[((size_t)bh * N_ + km) * U_ + lane])
           + __ldg(&g_O1[((size_t)bh * NC16 + c16) * U_ + lane]);
        p2 = __ldg(&g_P2[((size_t)bh * N_ + km) * U_ + lane])
           + __ldg(&g_O2[((size_t)bh * NC16 + c16) * U_ + lane]);
    }
    const float pt1 = __ldg(&g_Ptot1[bh * U_ + lane]);

    const float Z = ea * S2ex + eb * (S1t - S1ex);
    const float num = ea * p2 + eb * (pt1 - p1);
    const float val = num / Z + __ldg(&biases[h * U_ + lane]);

    out[((size_t)b * N_ + n) * (H_ * U_) + h * U_ + lane] = fmaxf(val, 0.f);
}

// ============================================================
extern "C" void kernel_launch(void* const* d_in, const int* in_sizes, int n_in,
                              void* d_out, int out_size) {
    const float* x      = (const float*)d_in[0];
    const float* kern   = (const float*)d_in[1];
    const float* att_s  = (const float*)d_in[2];
    const float* att_n  = (const float*)d_in[3];
    const float* biases = (const float*)d_in[4];
    float* out = (float*)d_out;

    k1_feats<<<dim3(N_ / 128, BH_), 128>>>(x, kern, att_s, att_n);
    k2_sort_scan<<<BH_, 1024>>>();
    k3a_chunk_prefix<<<dim3(BH_, 32), 256>>>();
    k3b_chunk_scan<<<BH_, 1024>>>();
    k4_output<<<(BH_ * N_) / 8, 256>>>(biases, out);
}